// round 13
// baseline (speedup 1.0000x reference)
#include <cuda_runtime.h>
#include <cuda_fp16.h>
#include <cstdint>

#define NSEQ 2048
#define DIN  1024
#define DOUT 1024
#define BATCH 8
#define NTOK  (BATCH * NSEQ)   // 16384

// ---------------- device scratch (no allocations allowed) ----------------
__device__ float g_S[(size_t)BATCH * NSEQ * NSEQ];
__device__ __half g_X [(size_t)NTOK * DIN];                 // x fp16
__device__ __half g_Wt[3ull * DOUT * DIN];                  // W^T fp16
__device__ __half g_Q [(size_t)NTOK * DOUT];                // Q fp16
__device__ __half g_K [(size_t)NTOK * DOUT];                // K fp16
__device__ __half g_Vt[(size_t)BATCH * DOUT * NSEQ];        // V^T fp16
__device__ __half g_P [(size_t)BATCH * NSEQ * NSEQ];        // P fp16

// ---------------- helpers ----------------
__device__ __forceinline__ uint32_t smem_u32(const void* p) {
    uint32_t a;
    asm("{ .reg .u64 t; cvta.to.shared.u64 t, %1; cvt.u32.u64 %0, t; }" : "=r"(a) : "l"(p));
    return a;
}
__device__ __forceinline__ void ldm_x4(uint32_t r[4], uint32_t addr) {
    asm volatile("ldmatrix.sync.aligned.m8n8.x4.shared.b16 {%0,%1,%2,%3}, [%4];"
                 : "=r"(r[0]), "=r"(r[1]), "=r"(r[2]), "=r"(r[3]) : "r"(addr));
}
__device__ __forceinline__ void mma16816(float* c, const uint32_t* a, const uint32_t* b) {
    asm volatile(
        "mma.sync.aligned.m16n8k16.row.col.f32.f16.f16.f32 "
        "{%0,%1,%2,%3}, {%4,%5,%6,%7}, {%8,%9}, {%0,%1,%2,%3};"
        : "+f"(c[0]), "+f"(c[1]), "+f"(c[2]), "+f"(c[3])
        : "r"(a[0]), "r"(a[1]), "r"(a[2]), "r"(a[3]), "r"(b[0]), "r"(b[1]));
}
#define CP16(dst, src) \
    asm volatile("cp.async.cg.shared.global [%0], [%1], 16;" :: "r"(dst), "l"(src))
#define CPCOMMIT() asm volatile("cp.async.commit_group;" ::: "memory")
#define CPWAIT1()  asm volatile("cp.async.wait_group 1;" ::: "memory")
#define CPWAIT0()  asm volatile("cp.async.wait_group 0;" ::: "memory")

__device__ __forceinline__ uint32_t pack2h(__half a, __half b) {
    return (uint32_t)__half_as_ushort(a) | ((uint32_t)__half_as_ushort(b) << 16);
}

// SMEM: 4-stage ring. Stage = A tile (128x32, 80B stride) + B tile. 20 KB/stage.
#define TBYTES   10240
#define OFF_B    10240
#define STG      20480
#define SMEM_SZ  (4 * STG)        // 81920 B -> 2 CTAs/SM (160 KB of 228)

// cp.async one tile (128x32 fp16)
__device__ __forceinline__ void stage_load(
    uint32_t sT, const __half* __restrict__ T, int ld, int base, int k0, int tid)
{
#pragma unroll
    for (int i = 0; i < 2; i++) {
        int idx = tid + i * 256;
        int row = idx >> 2;
        int c   = idx & 3;
        size_t g = (size_t)(base + row) * ld + k0 + c * 8;
        CP16(sT + row * 80 + c * 16, T + g);
    }
}

// ---------------- core GEMM: fp16 x fp16 -> fp32 ----------------
// 128x128 CTA tile, 8 warps (2M x 4N), warp tile 64x32, BK=32.
// 4-stage ring: one wait+barrier per TWO chunks, cross-barrier MMA holdback.
// Requires kEnd a multiple of 64 (true for all call sites here).
// EMODE: 0 = fp32 C, 1 = fp16 transposed (V^T), 2 = fp16 row-major (Q/K)
template <int EMODE>
__device__ __forceinline__ void gemm_h(
    const __half* __restrict__ AG, int lda, int aBase,
    const __half* __restrict__ BG, int ldb, int bBase, int kEnd,
    float* __restrict__ C, int ldOut, int oRow, int oCol,
    __half* __restrict__ OH)
{
    extern __shared__ char smem[];
    const int tid  = threadIdx.x;
    const int wid  = tid >> 5;
    const int lane = tid & 31;
    const int warpM = (wid >> 2) * 64;
    const int warpN = (wid & 3) * 32;

    const uint32_t sb = smem_u32(smem);
    const uint32_t stB[4] = { sb, sb + STG, sb + 2 * STG, sb + 3 * STG };

    const uint32_t aOff = (uint32_t)(warpM + (lane & 15)) * 80 + ((lane >> 4) << 4);
    const uint32_t bOff = (uint32_t)(warpN + (lane & 7) + ((lane & 16) >> 1)) * 80 +
                          ((lane & 8) << 1);

    float acc[4][4][4];
#pragma unroll
    for (int i = 0; i < 4; i++)
#pragma unroll
        for (int j = 0; j < 4; j++)
#pragma unroll
            for (int e = 0; e < 4; e++) acc[i][j][e] = 0.0f;

    uint32_t f0a[4][4], f0b[4][2], f1a[4][4], f1b[4][2];

#define LOADF(fa, fb, stg, ko)                                               \
    {                                                                        \
        const uint32_t _ab = (stg) + (ko);                                   \
        const uint32_t _bb = (stg) + OFF_B + (ko);                           \
        _Pragma("unroll")                                                    \
        for (int mi = 0; mi < 4; mi++)                                       \
            ldm_x4((fa)[mi], _ab + aOff + (uint32_t)mi * (16 * 80));         \
        _Pragma("unroll")                                                    \
        for (int n2 = 0; n2 < 2; n2++) {                                     \
            uint32_t r[4];                                                   \
            ldm_x4(r, _bb + bOff + (uint32_t)n2 * (16 * 80));                \
            (fb)[n2 * 2][0] = r[0]; (fb)[n2 * 2][1] = r[1];                  \
            (fb)[n2 * 2 + 1][0] = r[2]; (fb)[n2 * 2 + 1][1] = r[3];          \
        }                                                                    \
    }
#define MMA_GRP(fa, fb)                                                      \
    {                                                                        \
        _Pragma("unroll")                                                    \
        for (int mi = 0; mi < 4; mi++)                                       \
            _Pragma("unroll")                                                \
            for (int ni = 0; ni < 4; ni++)                                   \
                mma16816(acc[mi][ni], (fa)[mi], (fb)[ni]);                   \
    }

    const int NC = kEnd >> 5;          // even (kEnd % 64 == 0)
    const int NP = NC >> 1;            // pairs of chunks

    // prologue: pair 0 -> stages {0,1}, pair 1 -> stages {2,3}
    stage_load(stB[0],         AG, lda, aBase, 0,  tid);
    stage_load(stB[0] + OFF_B, BG, ldb, bBase, 0,  tid);
    stage_load(stB[1],         AG, lda, aBase, 32, tid);
    stage_load(stB[1] + OFF_B, BG, ldb, bBase, 32, tid);
    CPCOMMIT();
    if (NP > 1) {
        stage_load(stB[2],         AG, lda, aBase, 64, tid);
        stage_load(stB[2] + OFF_B, BG, ldb, bBase, 64, tid);
        stage_load(stB[3],         AG, lda, aBase, 96, tid);
        stage_load(stB[3] + OFF_B, BG, ldb, bBase, 96, tid);
        CPCOMMIT();
        CPWAIT1();                      // pair 0 complete
    } else {
        CPWAIT0();
    }
    __syncthreads();
    LOADF(f0a, f0b, stB[0], 0);

    for (int p = 0; p < NP; p++) {
        const uint32_t c0 = stB[(p & 1) * 2];
        const uint32_t c1 = stB[(p & 1) * 2 + 1];
        const uint32_t n0 = stB[((p & 1) ^ 1) * 2];

        // three barrier-free groups over chunks 2p, 2p+1
        LOADF(f1a, f1b, c0, 32);
        MMA_GRP(f0a, f0b);
        LOADF(f0a, f0b, c1, 0);
        MMA_GRP(f1a, f1b);
        LOADF(f1a, f1b, c1, 32);
        MMA_GRP(f0a, f0b);

        CPWAIT0();                      // pair p+1 complete (issued 1 iter ago)
        __syncthreads();                // visible to all; cur stages read-done

        if (p + 1 < NP) {
            // post-barrier LDSM burst — covered by the held-back MMA group
            LOADF(f0a, f0b, n0, 0);
        }
        MMA_GRP(f1a, f1b);

        if (p + 2 < NP) {
            // refill cur stages with pair p+2 (all reads completed pre-barrier)
            const int k0 = (p + 2) << 6;
            stage_load(c0,         AG, lda, aBase, k0,      tid);
            stage_load(c0 + OFF_B, BG, ldb, bBase, k0,      tid);
            stage_load(c1,         AG, lda, aBase, k0 + 32, tid);
            stage_load(c1 + OFF_B, BG, ldb, bBase, k0 + 32, tid);
            CPCOMMIT();
        }
    }

#undef LOADF
#undef MMA_GRP

    // ---------------- epilogue ----------------
    const int mBase = warpM + (lane >> 2);
    const int nBase = warpN + (lane & 3) * 2;
    if (EMODE == 0) {
#pragma unroll
        for (int mi = 0; mi < 4; mi++)
#pragma unroll
            for (int ni = 0; ni < 4; ni++) {
                const float* cp = acc[mi][ni];
                int r0 = oRow + mBase + mi * 16;
                int cc = oCol + nBase + ni * 8;
                *(float2*)&C[(size_t)r0 * ldOut + cc]       = make_float2(cp[0], cp[1]);
                *(float2*)&C[(size_t)(r0 + 8) * ldOut + cc] = make_float2(cp[2], cp[3]);
            }
    } else if (EMODE == 2) {
        // fp16 row-major (Q, K)
#pragma unroll
        for (int mi = 0; mi < 4; mi++)
#pragma unroll
            for (int ni = 0; ni < 4; ni++) {
                const float* cp = acc[mi][ni];
#pragma unroll
                for (int h = 0; h < 2; h++) {
                    int r0 = oRow + mBase + mi * 16 + h * 8;
                    int cc = oCol + nBase + ni * 8;
                    uint32_t p = pack2h(__float2half_rn(cp[h * 2]),
                                        __float2half_rn(cp[h * 2 + 1]));
                    *(uint32_t*)&OH[(size_t)r0 * ldOut + cc] = p;
                }
            }
    } else {
        // fp16 transposed (V^T): (seq=row, e=col) -> Vt[b][e][seq]
#pragma unroll
        for (int mi = 0; mi < 4; mi++)
#pragma unroll
            for (int ni = 0; ni < 4; ni++) {
                const float* cp = acc[mi][ni];
#pragma unroll
                for (int e = 0; e < 4; e++) {
                    int row = oRow + mBase + mi * 16 + (e >> 1) * 8;
                    int col = oCol + nBase + ni * 8 + (e & 1);
                    int b = row >> 11, nloc = row & (NSEQ - 1);
                    size_t o = ((size_t)b * DOUT + col) * NSEQ + nloc;
                    OH[o] = __float2half_rn(cp[e]);
                }
            }
    }
}

// ---------------- kernels ----------------

// Round x to fp16.
__global__ void __launch_bounds__(256) xround_kernel(const float* __restrict__ X)
{
    size_t i4 = (size_t)blockIdx.x * 256 + threadIdx.x;
    float4 v = *(const float4*)&X[i4 * 4];
    uint32_t p0 = pack2h(__float2half_rn(v.x), __float2half_rn(v.y));
    uint32_t p1 = pack2h(__float2half_rn(v.z), __float2half_rn(v.w));
    *(uint2*)&g_X[i4 * 4] = make_uint2(p0, p1);
}

// Transpose + round weights to fp16: Wt[z][dout][din]
__global__ void __launch_bounds__(256) wtrans_kernel(
    const float* __restrict__ Wq, const float* __restrict__ Wk, const float* __restrict__ Wv)
{
    const int z = blockIdx.z;
    const float* W = (z == 0) ? Wq : (z == 1) ? Wk : Wv;
    __half* T = g_Wt + (size_t)z * DOUT * DIN;

    __shared__ float t[32][33];
    const int j0 = blockIdx.x * 32;
    const int i0 = blockIdx.y * 32;
    const int tx = threadIdx.x & 31, ty = threadIdx.x >> 5;
#pragma unroll
    for (int k = 0; k < 4; k++)
        t[ty + k * 8][tx] = W[(size_t)(i0 + ty + k * 8) * DOUT + j0 + tx];
    __syncthreads();
#pragma unroll
    for (int k = 0; k < 4; k++) {
        size_t o = (size_t)(j0 + ty + k * 8) * DIN + i0 + tx;
        T[o] = __float2half_rn(t[tx][ty + k * 8]);
    }
}

// QKV: z=0 -> Q, z=1 -> K, z=2 -> V^T
__global__ void __launch_bounds__(256, 2) qkv_kernel()
{
    const int z = blockIdx.z;
    const __half* w = g_Wt + (size_t)z * DOUT * DIN;
    const int rowBase = blockIdx.y * 128;
    const int colBase = blockIdx.x * 128;
    if (z == 2)
        gemm_h<1>(g_X, DIN, rowBase, w, DIN, colBase, DIN,
                  nullptr, 0, rowBase, colBase, g_Vt);
    else
        gemm_h<2>(g_X, DIN, rowBase, w, DIN, colBase, DIN,
                  nullptr, DOUT, rowBase, colBase, (z == 0) ? g_Q : g_K);
}

// Scores S = Q K^T (causal tile skip). Longest rows (high qT) launch first.
__global__ void __launch_bounds__(256, 2) score_kernel()
{
    const int b = blockIdx.z;
    const int qT = (int)(gridDim.y - 1) - blockIdx.y;   // descending work order
    const int kT = blockIdx.x;
    if (kT > qT) return;
    gemm_h<0>(g_Q, DOUT, b * NSEQ + qT * 128,
              g_K, DOUT, b * NSEQ + kT * 128, DOUT,
              g_S + (size_t)b * NSEQ * NSEQ, NSEQ, qT * 128, kT * 128,
              nullptr);
}

// Causal softmax; writes fp16 P zero-filled to 128-aligned boundary.
__global__ void __launch_bounds__(256) softmax_kernel()
{
    const int row = blockIdx.x;
    const int b = row >> 11;
    const int q = row & (NSEQ - 1);
    const size_t rb = (size_t)b * NSEQ * NSEQ + (size_t)q * NSEQ;
    const float* s = g_S + rb;

    const int len = q + 1;
    const int alignedOut = (len + 127) & ~127;

    float v[8];
    float m = -1e30f;
#pragma unroll
    for (int i = 0; i < 2; i++) {
        int base = (threadIdx.x + i * 256) * 4;
        if (base < alignedOut) {
            float4 x = *(const float4*)&s[base];
            v[i * 4 + 0] = (base + 0 < len) ? x.x * 0.03125f : -1e30f;
            v[i * 4 + 1] = (base + 1 < len) ? x.y * 0.03125f : -1e30f;
            v[i * 4 + 2] = (base + 2 < len) ? x.z * 0.03125f : -1e30f;
            v[i * 4 + 3] = (base + 3 < len) ? x.w * 0.03125f : -1e30f;
        } else {
            v[i * 4] = v[i * 4 + 1] = v[i * 4 + 2] = v[i * 4 + 3] = -1e30f;
        }
#pragma unroll
        for (int e = 0; e < 4; e++) m = fmaxf(m, v[i * 4 + e]);
    }

    __shared__ float red[256];
    red[threadIdx.x] = m;
    __syncthreads();
#pragma unroll
    for (int off = 128; off > 0; off >>= 1) {
        if (threadIdx.x < off)
            red[threadIdx.x] = fmaxf(red[threadIdx.x], red[threadIdx.x + off]);
        __syncthreads();
    }
    m = red[0];
    __syncthreads();

    float sum = 0.0f;
#pragma unroll
    for (int i = 0; i < 8; i++) {
        float e = __expf(v[i] - m);
        v[i] = e;
        sum += e;
    }
    red[threadIdx.x] = sum;
    __syncthreads();
#pragma unroll
    for (int off = 128; off > 0; off >>= 1) {
        if (threadIdx.x < off)
            red[threadIdx.x] += red[threadIdx.x + off];
        __syncthreads();
    }
    const float inv = 1.0f / red[0];

#pragma unroll
    for (int i = 0; i < 2; i++) {
        int base = (threadIdx.x + i * 256) * 4;
        if (base < alignedOut) {
            uint32_t p0 = pack2h(__float2half_rn(v[i * 4] * inv),
                                 __float2half_rn(v[i * 4 + 1] * inv));
            uint32_t p1 = pack2h(__float2half_rn(v[i * 4 + 2] * inv),
                                 __float2half_rn(v[i * 4 + 3] * inv));
            *(uint2*)&g_P[rb + base] = make_uint2(p0, p1);
        }
    }
}

// context = P V, causal K extent. Longest-K CTAs (high qT) launch first.
__global__ void __launch_bounds__(256, 2) pv_kernel(float* __restrict__ out)
{
    const int b = blockIdx.z;
    const int qT = (int)(gridDim.y - 1) - blockIdx.y;   // descending work order
    gemm_h<0>(g_P, NSEQ, b * NSEQ + qT * 128,
              g_Vt, NSEQ, b * DOUT + blockIdx.x * 128,
              (qT + 1) * 128,
              out + (size_t)b * NSEQ * DOUT, DOUT, qT * 128, blockIdx.x * 128,
              nullptr);
}

// ---------------- launch ----------------
extern "C" void kernel_launch(void* const* d_in, const int* in_sizes, int n_in,
                              void* d_out, int out_size)
{
    (void)in_sizes; (void)n_in; (void)out_size;
    const float* x  = (const float*)d_in[0];
    const float* Wq = (const float*)d_in[1];
    const float* Wk = (const float*)d_in[2];
    const float* Wv = (const float*)d_in[3];
    float* out = (float*)d_out;

    cudaFuncSetAttribute(qkv_kernel,   cudaFuncAttributeMaxDynamicSharedMemorySize, SMEM_SZ);
    cudaFuncSetAttribute(score_kernel, cudaFuncAttributeMaxDynamicSharedMemorySize, SMEM_SZ);
    cudaFuncSetAttribute(pv_kernel,    cudaFuncAttributeMaxDynamicSharedMemorySize, SMEM_SZ);

    xround_kernel<<<NTOK * DIN / 1024, 256>>>(x);
    wtrans_kernel<<<dim3(32, 32, 3), 256>>>(Wq, Wk, Wv);
    qkv_kernel<<<dim3(DOUT / 128, NTOK / 128, 3), 256, SMEM_SZ>>>();
    score_kernel<<<dim3(NSEQ / 128, NSEQ / 128, BATCH), 256, SMEM_SZ>>>();
    softmax_kernel<<<BATCH * NSEQ, 256>>>();
    pv_kernel<<<dim3(DOUT / 128, NSEQ / 128, BATCH), 256, SMEM_SZ>>>(out);
}

// round 14
// speedup vs baseline: 1.0179x; 1.0179x over previous
#include <cuda_runtime.h>
#include <cuda_fp16.h>
#include <cstdint>

#define NSEQ 2048
#define DIN  1024
#define DOUT 1024
#define BATCH 8
#define NTOK  (BATCH * NSEQ)   // 16384

// ---------------- device scratch (no allocations allowed) ----------------
__device__ float g_S[(size_t)BATCH * NSEQ * NSEQ];
__device__ __half g_X [(size_t)NTOK * DIN];                 // x fp16
__device__ __half g_Wt[3ull * DOUT * DIN];                  // W^T fp16
__device__ __half g_Q [(size_t)NTOK * DOUT];                // Q fp16
__device__ __half g_K [(size_t)NTOK * DOUT];                // K fp16
__device__ __half g_Vt[(size_t)BATCH * DOUT * NSEQ];        // V^T fp16
__device__ __half g_P [(size_t)BATCH * NSEQ * NSEQ];        // P fp16

// ---------------- helpers ----------------
__device__ __forceinline__ uint32_t smem_u32(const void* p) {
    uint32_t a;
    asm("{ .reg .u64 t; cvta.to.shared.u64 t, %1; cvt.u32.u64 %0, t; }" : "=r"(a) : "l"(p));
    return a;
}
__device__ __forceinline__ void ldm_x4(uint32_t r[4], uint32_t addr) {
    asm volatile("ldmatrix.sync.aligned.m8n8.x4.shared.b16 {%0,%1,%2,%3}, [%4];"
                 : "=r"(r[0]), "=r"(r[1]), "=r"(r[2]), "=r"(r[3]) : "r"(addr));
}
__device__ __forceinline__ void mma16816(float* c, const uint32_t* a, const uint32_t* b) {
    asm volatile(
        "mma.sync.aligned.m16n8k16.row.col.f32.f16.f16.f32 "
        "{%0,%1,%2,%3}, {%4,%5,%6,%7}, {%8,%9}, {%0,%1,%2,%3};"
        : "+f"(c[0]), "+f"(c[1]), "+f"(c[2]), "+f"(c[3])
        : "r"(a[0]), "r"(a[1]), "r"(a[2]), "r"(a[3]), "r"(b[0]), "r"(b[1]));
}
#define CP16(dst, src) \
    asm volatile("cp.async.cg.shared.global [%0], [%1], 16;" :: "r"(dst), "l"(src))
#define CPCOMMIT() asm volatile("cp.async.commit_group;" ::: "memory")
#define CPWAIT1()  asm volatile("cp.async.wait_group 1;" ::: "memory")
#define CPWAIT0()  asm volatile("cp.async.wait_group 0;" ::: "memory")

__device__ __forceinline__ uint32_t pack2h(__half a, __half b) {
    return (uint32_t)__half_as_ushort(a) | ((uint32_t)__half_as_ushort(b) << 16);
}

// SMEM: 3-stage ring. Stage = A tile (128x32, 80B stride) + B tile. 20 KB/stage.
#define TBYTES   10240
#define OFF_B    10240
#define STG      20480
#define SMEM_SZ  (3 * STG)        // 61440 B -> 2 CTAs/SM

// cp.async one tile (128x32 fp16)
__device__ __forceinline__ void stage_load(
    uint32_t sT, const __half* __restrict__ T, int ld, int base, int k0, int tid)
{
#pragma unroll
    for (int i = 0; i < 2; i++) {
        int idx = tid + i * 256;
        int row = idx >> 2;
        int c   = idx & 3;
        size_t g = (size_t)(base + row) * ld + k0 + c * 8;
        CP16(sT + row * 80 + c * 16, T + g);
    }
}

// ---------------- core GEMM: fp16 x fp16 -> fp32 (R12 schedule) ----------------
// 128x128 CTA tile, 8 warps (2M x 4N), warp tile 64x32, BK=32.
// 3-stage cp.async ring + cross-barrier MMA holdback.
// EMODE: 0 = fp32 C (scaled by CSCALE), 1 = fp16 transposed (V^T), 2 = fp16 row-major
template <int EMODE, bool SCALE = false>
__device__ __forceinline__ void gemm_h(
    const __half* __restrict__ AG, int lda, int aBase,
    const __half* __restrict__ BG, int ldb, int bBase, int kEnd,
    float* __restrict__ C, int ldOut, int oRow, int oCol,
    __half* __restrict__ OH)
{
    extern __shared__ char smem[];
    const int tid  = threadIdx.x;
    const int wid  = tid >> 5;
    const int lane = tid & 31;
    const int warpM = (wid >> 2) * 64;
    const int warpN = (wid & 3) * 32;

    const uint32_t sb = smem_u32(smem);
    const uint32_t stB[3] = { sb, sb + STG, sb + 2 * STG };

    const uint32_t aOff = (uint32_t)(warpM + (lane & 15)) * 80 + ((lane >> 4) << 4);
    const uint32_t bOff = (uint32_t)(warpN + (lane & 7) + ((lane & 16) >> 1)) * 80 +
                          ((lane & 8) << 1);

    float acc[4][4][4];
#pragma unroll
    for (int i = 0; i < 4; i++)
#pragma unroll
        for (int j = 0; j < 4; j++)
#pragma unroll
            for (int e = 0; e < 4; e++) acc[i][j][e] = 0.0f;

    uint32_t f0a[4][4], f0b[4][2], f1a[4][4], f1b[4][2];

#define LOADF(fa, fb, stg, ko)                                               \
    {                                                                        \
        const uint32_t _ab = (stg) + (ko);                                   \
        const uint32_t _bb = (stg) + OFF_B + (ko);                           \
        _Pragma("unroll")                                                    \
        for (int mi = 0; mi < 4; mi++)                                       \
            ldm_x4((fa)[mi], _ab + aOff + (uint32_t)mi * (16 * 80));         \
        _Pragma("unroll")                                                    \
        for (int n2 = 0; n2 < 2; n2++) {                                     \
            uint32_t r[4];                                                   \
            ldm_x4(r, _bb + bOff + (uint32_t)n2 * (16 * 80));                \
            (fb)[n2 * 2][0] = r[0]; (fb)[n2 * 2][1] = r[1];                  \
            (fb)[n2 * 2 + 1][0] = r[2]; (fb)[n2 * 2 + 1][1] = r[3];          \
        }                                                                    \
    }
#define MMA_GRP(fa, fb)                                                      \
    {                                                                        \
        _Pragma("unroll")                                                    \
        for (int mi = 0; mi < 4; mi++)                                       \
            _Pragma("unroll")                                                \
            for (int ni = 0; ni < 4; ni++)                                   \
                mma16816(acc[mi][ni], (fa)[mi], (fb)[ni]);                   \
    }

    const int NC = kEnd >> 5;

    // prologue: stage chunks 0 and 1, then load f0 = (chunk0, ks0)
    stage_load(stB[0],         AG, lda, aBase, 0, tid);
    stage_load(stB[0] + OFF_B, BG, ldb, bBase, 0, tid);
    CPCOMMIT();
    if (NC > 1) {
        stage_load(stB[1],         AG, lda, aBase, 32, tid);
        stage_load(stB[1] + OFF_B, BG, ldb, bBase, 32, tid);
        CPCOMMIT();
        CPWAIT1();
    } else {
        CPWAIT0();
    }
    __syncthreads();
    LOADF(f0a, f0b, stB[0], 0);

    int sCur = 0, sNxt = 1, sFar = 2;   // stages of chunks c, c+1, c+2
    for (int c = 0; c < NC; c++) {
        // ks1 of chunk c (covered by MMA(f0) below)
        LOADF(f1a, f1b, stB[sCur], 32);
        MMA_GRP(f0a, f0b);

        // prefetch chunk c+2 into the far stage
        if (c + 2 < NC) {
            const int k0 = (c + 2) << 5;
            stage_load(stB[sFar],         AG, lda, aBase, k0, tid);
            stage_load(stB[sFar] + OFF_B, BG, ldb, bBase, k0, tid);
            CPCOMMIT();
            CPWAIT1();             // ensures chunk c+1 data arrived
        } else {
            CPWAIT0();             // tail: drain everything
        }
        __syncthreads();           // stage sNxt visible to all; sFar free to refill

        if (c + 1 < NC) {
            // post-barrier LDSM burst — covered by MMA(f1) right after
            LOADF(f0a, f0b, stB[sNxt], 0);
        }
        MMA_GRP(f1a, f1b);

        int t = sCur; sCur = sNxt; sNxt = sFar; sFar = t;
    }

#undef LOADF
#undef MMA_GRP

    // ---------------- epilogue ----------------
    const int mBase = warpM + (lane >> 2);
    const int nBase = warpN + (lane & 3) * 2;
    if (EMODE == 0) {
        const float sc = SCALE ? 0.03125f : 1.0f;
#pragma unroll
        for (int mi = 0; mi < 4; mi++)
#pragma unroll
            for (int ni = 0; ni < 4; ni++) {
                const float* cp = acc[mi][ni];
                int r0 = oRow + mBase + mi * 16;
                int cc = oCol + nBase + ni * 8;
                *(float2*)&C[(size_t)r0 * ldOut + cc]       = make_float2(cp[0] * sc, cp[1] * sc);
                *(float2*)&C[(size_t)(r0 + 8) * ldOut + cc] = make_float2(cp[2] * sc, cp[3] * sc);
            }
    } else if (EMODE == 2) {
        // fp16 row-major (Q, K)
#pragma unroll
        for (int mi = 0; mi < 4; mi++)
#pragma unroll
            for (int ni = 0; ni < 4; ni++) {
                const float* cp = acc[mi][ni];
#pragma unroll
                for (int h = 0; h < 2; h++) {
                    int r0 = oRow + mBase + mi * 16 + h * 8;
                    int cc = oCol + nBase + ni * 8;
                    uint32_t p = pack2h(__float2half_rn(cp[h * 2]),
                                        __float2half_rn(cp[h * 2 + 1]));
                    *(uint32_t*)&OH[(size_t)r0 * ldOut + cc] = p;
                }
            }
    } else {
        // fp16 transposed (V^T): (seq=row, e=col) -> Vt[b][e][seq]
#pragma unroll
        for (int mi = 0; mi < 4; mi++)
#pragma unroll
            for (int ni = 0; ni < 4; ni++) {
                const float* cp = acc[mi][ni];
#pragma unroll
                for (int e = 0; e < 4; e++) {
                    int row = oRow + mBase + mi * 16 + (e >> 1) * 8;
                    int col = oCol + nBase + ni * 8 + (e & 1);
                    int b = row >> 11, nloc = row & (NSEQ - 1);
                    size_t o = ((size_t)b * DOUT + col) * NSEQ + nloc;
                    OH[o] = __float2half_rn(cp[e]);
                }
            }
    }
}

// ---------------- kernels ----------------

// Merged prep: blocks [0, 16384) round x to fp16; blocks [16384, 19456)
// transpose+round the weights. One launch, overlapping both.
#define XBLOCKS (NTOK * DIN / 1024)   // 16384
__global__ void __launch_bounds__(256) prep_kernel(
    const float* __restrict__ X,
    const float* __restrict__ Wq, const float* __restrict__ Wk, const float* __restrict__ Wv)
{
    const int bid = blockIdx.x;
    if (bid < XBLOCKS) {
        size_t i4 = (size_t)bid * 256 + threadIdx.x;
        float4 v = *(const float4*)&X[i4 * 4];
        uint32_t p0 = pack2h(__float2half_rn(v.x), __float2half_rn(v.y));
        uint32_t p1 = pack2h(__float2half_rn(v.z), __float2half_rn(v.w));
        *(uint2*)&g_X[i4 * 4] = make_uint2(p0, p1);
        return;
    }
    const int w = bid - XBLOCKS;          // 0..3071
    const int z = w >> 10;                // /1024
    const int rem = w & 1023;
    const int j0 = (rem & 31) * 32;       // dout
    const int i0 = (rem >> 5) * 32;       // din
    const float* W = (z == 0) ? Wq : (z == 1) ? Wk : Wv;
    __half* T = g_Wt + (size_t)z * DOUT * DIN;

    __shared__ float t[32][33];
    const int tx = threadIdx.x & 31, ty = threadIdx.x >> 5;
#pragma unroll
    for (int k = 0; k < 4; k++)
        t[ty + k * 8][tx] = W[(size_t)(i0 + ty + k * 8) * DOUT + j0 + tx];
    __syncthreads();
#pragma unroll
    for (int k = 0; k < 4; k++) {
        size_t o = (size_t)(j0 + ty + k * 8) * DIN + i0 + tx;
        T[o] = __float2half_rn(t[tx][ty + k * 8]);
    }
}

// QKV: z=0 -> Q, z=1 -> K, z=2 -> V^T
__global__ void __launch_bounds__(256, 2) qkv_kernel()
{
    const int z = blockIdx.z;
    const __half* w = g_Wt + (size_t)z * DOUT * DIN;
    const int rowBase = blockIdx.y * 128;
    const int colBase = blockIdx.x * 128;
    if (z == 2)
        gemm_h<1>(g_X, DIN, rowBase, w, DIN, colBase, DIN,
                  nullptr, 0, rowBase, colBase, g_Vt);
    else
        gemm_h<2>(g_X, DIN, rowBase, w, DIN, colBase, DIN,
                  nullptr, DOUT, rowBase, colBase, (z == 0) ? g_Q : g_K);
}

// Scores S = (Q K^T) * 1/32 — compacted triangular grid, descending-qT (LPT).
// grid.x = 136 active tiles (16*17/2), grid.z = batch.
#define NTILES 136
__global__ void __launch_bounds__(256, 2) score_kernel()
{
    const int b = blockIdx.z;
    const int t = (NTILES - 1) - (int)blockIdx.x;       // descending work order
    // triangular decode: qT = largest q with q(q+1)/2 <= t
    int qT = (int)((sqrtf(8.0f * (float)t + 1.0f) - 1.0f) * 0.5f);
    while ((qT + 1) * (qT + 2) / 2 <= t) qT++;
    while (qT * (qT + 1) / 2 > t) qT--;
    const int kT = t - qT * (qT + 1) / 2;

    gemm_h<0, true>(g_Q, DOUT, b * NSEQ + qT * 128,
                    g_K, DOUT, b * NSEQ + kT * 128, DOUT,
                    g_S + (size_t)b * NSEQ * NSEQ, NSEQ, qT * 128, kT * 128,
                    nullptr);
}

// Causal softmax over pre-scaled S; writes fp16 P zero-filled to 128 boundary.
__global__ void __launch_bounds__(256) softmax_kernel()
{
    const int row = blockIdx.x;
    const int b = row >> 11;
    const int q = row & (NSEQ - 1);
    const size_t rb = (size_t)b * NSEQ * NSEQ + (size_t)q * NSEQ;
    const float* s = g_S + rb;

    const int len = q + 1;
    const int alignedOut = (len + 127) & ~127;

    float v[8];
    float m = -1e30f;
#pragma unroll
    for (int i = 0; i < 2; i++) {
        int base = (threadIdx.x + i * 256) * 4;
        if (base < alignedOut) {
            float4 x = *(const float4*)&s[base];
            v[i * 4 + 0] = (base + 0 < len) ? x.x : -1e30f;
            v[i * 4 + 1] = (base + 1 < len) ? x.y : -1e30f;
            v[i * 4 + 2] = (base + 2 < len) ? x.z : -1e30f;
            v[i * 4 + 3] = (base + 3 < len) ? x.w : -1e30f;
        } else {
            v[i * 4] = v[i * 4 + 1] = v[i * 4 + 2] = v[i * 4 + 3] = -1e30f;
        }
#pragma unroll
        for (int e = 0; e < 4; e++) m = fmaxf(m, v[i * 4 + e]);
    }

    __shared__ float red[256];
    red[threadIdx.x] = m;
    __syncthreads();
#pragma unroll
    for (int off = 128; off > 0; off >>= 1) {
        if (threadIdx.x < off)
            red[threadIdx.x] = fmaxf(red[threadIdx.x], red[threadIdx.x + off]);
        __syncthreads();
    }
    m = red[0];
    __syncthreads();

    float sum = 0.0f;
#pragma unroll
    for (int i = 0; i < 8; i++) {
        float e = __expf(v[i] - m);
        v[i] = e;
        sum += e;
    }
    red[threadIdx.x] = sum;
    __syncthreads();
#pragma unroll
    for (int off = 128; off > 0; off >>= 1) {
        if (threadIdx.x < off)
            red[threadIdx.x] += red[threadIdx.x + off];
        __syncthreads();
    }
    const float inv = 1.0f / red[0];

#pragma unroll
    for (int i = 0; i < 2; i++) {
        int base = (threadIdx.x + i * 256) * 4;
        if (base < alignedOut) {
            uint32_t p0 = pack2h(__float2half_rn(v[i * 4] * inv),
                                 __float2half_rn(v[i * 4 + 1] * inv));
            uint32_t p1 = pack2h(__float2half_rn(v[i * 4 + 2] * inv),
                                 __float2half_rn(v[i * 4 + 3] * inv));
            *(uint2*)&g_P[rb + base] = make_uint2(p0, p1);
        }
    }
}

// context = P V, causal K extent. Longest-K CTAs (high qT) launch first.
__global__ void __launch_bounds__(256, 2) pv_kernel(float* __restrict__ out)
{
    const int b = blockIdx.z;
    const int qT = (int)(gridDim.y - 1) - blockIdx.y;   // descending work order
    gemm_h<0>(g_P, NSEQ, b * NSEQ + qT * 128,
              g_Vt, NSEQ, b * DOUT + blockIdx.x * 128,
              (qT + 1) * 128,
              out + (size_t)b * NSEQ * DOUT, DOUT, qT * 128, blockIdx.x * 128,
              nullptr);
}

// ---------------- launch ----------------
extern "C" void kernel_launch(void* const* d_in, const int* in_sizes, int n_in,
                              void* d_out, int out_size)
{
    (void)in_sizes; (void)n_in; (void)out_size;
    const float* x  = (const float*)d_in[0];
    const float* Wq = (const float*)d_in[1];
    const float* Wk = (const float*)d_in[2];
    const float* Wv = (const float*)d_in[3];
    float* out = (float*)d_out;

    cudaFuncSetAttribute(qkv_kernel,   cudaFuncAttributeMaxDynamicSharedMemorySize, SMEM_SZ);
    cudaFuncSetAttribute(score_kernel, cudaFuncAttributeMaxDynamicSharedMemorySize, SMEM_SZ);
    cudaFuncSetAttribute(pv_kernel,    cudaFuncAttributeMaxDynamicSharedMemorySize, SMEM_SZ);

    prep_kernel<<<XBLOCKS + 3072, 256>>>(x, Wq, Wk, Wv);
    qkv_kernel<<<dim3(DOUT / 128, NTOK / 128, 3), 256, SMEM_SZ>>>();
    score_kernel<<<dim3(NTILES, 1, BATCH), 256, SMEM_SZ>>>();
    softmax_kernel<<<BATCH * NSEQ, 256>>>();
    pv_kernel<<<dim3(DOUT / 128, NSEQ / 128, BATCH), 256, SMEM_SZ>>>(out);
}

// round 15
// speedup vs baseline: 1.0193x; 1.0014x over previous
#include <cuda_runtime.h>
#include <cuda_fp16.h>
#include <cstdint>

#define NSEQ 2048
#define DIN  1024
#define DOUT 1024
#define BATCH 8
#define NTOK  (BATCH * NSEQ)   // 16384

// ---------------- device scratch (no allocations allowed) ----------------
__device__ float g_S[(size_t)BATCH * NSEQ * NSEQ];
__device__ __half g_X [(size_t)NTOK * DIN];                 // x fp16
__device__ __half g_Wt[3ull * DOUT * DIN];                  // W^T fp16
__device__ __half g_Q [(size_t)NTOK * DOUT];                // Q fp16
__device__ __half g_K [(size_t)NTOK * DOUT];                // K fp16
__device__ __half g_Vt[(size_t)BATCH * DOUT * NSEQ];        // V^T fp16
__device__ __half g_P [(size_t)BATCH * NSEQ * NSEQ];        // P fp16

// ---------------- helpers ----------------
__device__ __forceinline__ uint32_t smem_u32(const void* p) {
    uint32_t a;
    asm("{ .reg .u64 t; cvta.to.shared.u64 t, %1; cvt.u32.u64 %0, t; }" : "=r"(a) : "l"(p));
    return a;
}
__device__ __forceinline__ void ldm_x4(uint32_t r[4], uint32_t addr) {
    asm volatile("ldmatrix.sync.aligned.m8n8.x4.shared.b16 {%0,%1,%2,%3}, [%4];"
                 : "=r"(r[0]), "=r"(r[1]), "=r"(r[2]), "=r"(r[3]) : "r"(addr));
}
__device__ __forceinline__ void mma16816(float* c, const uint32_t* a, const uint32_t* b) {
    asm volatile(
        "mma.sync.aligned.m16n8k16.row.col.f32.f16.f16.f32 "
        "{%0,%1,%2,%3}, {%4,%5,%6,%7}, {%8,%9}, {%0,%1,%2,%3};"
        : "+f"(c[0]), "+f"(c[1]), "+f"(c[2]), "+f"(c[3])
        : "r"(a[0]), "r"(a[1]), "r"(a[2]), "r"(a[3]), "r"(b[0]), "r"(b[1]));
}
#define CP16(dst, src) \
    asm volatile("cp.async.cg.shared.global [%0], [%1], 16;" :: "r"(dst), "l"(src))
#define CPCOMMIT() asm volatile("cp.async.commit_group;" ::: "memory")
#define CPWAIT1()  asm volatile("cp.async.wait_group 1;" ::: "memory")
#define CPWAIT0()  asm volatile("cp.async.wait_group 0;" ::: "memory")

__device__ __forceinline__ uint32_t pack2h(__half a, __half b) {
    return (uint32_t)__half_as_ushort(a) | ((uint32_t)__half_as_ushort(b) << 16);
}

// SMEM: 3-stage ring. Stage = A tile (128x32, 80B stride) + B tile. 20 KB/stage.
#define TBYTES   10240
#define OFF_B    10240
#define STG      20480
#define SMEM_SZ  (3 * STG)        // 61440 B -> 2 CTAs/SM

// cp.async one tile (128x32 fp16)
__device__ __forceinline__ void stage_load(
    uint32_t sT, const __half* __restrict__ T, int ld, int base, int k0, int tid)
{
#pragma unroll
    for (int i = 0; i < 2; i++) {
        int idx = tid + i * 256;
        int row = idx >> 2;
        int c   = idx & 3;
        size_t g = (size_t)(base + row) * ld + k0 + c * 8;
        CP16(sT + row * 80 + c * 16, T + g);
    }
}

// ---------------- core GEMM: fp16 x fp16 -> fp32 (R12 schedule) ----------------
// 128x128 CTA tile, 8 warps (2M x 4N), warp tile 64x32, BK=32.
// 3-stage cp.async ring + cross-barrier MMA holdback.
// EMODE: 0 = fp32 C (optionally scaled), 1 = fp16 transposed (V^T), 2 = fp16 row-major
template <int EMODE, bool SCALE = false>
__device__ __forceinline__ void gemm_h(
    const __half* __restrict__ AG, int lda, int aBase,
    const __half* __restrict__ BG, int ldb, int bBase, int kEnd,
    float* __restrict__ C, int ldOut, int oRow, int oCol,
    __half* __restrict__ OH)
{
    extern __shared__ char smem[];
    const int tid  = threadIdx.x;
    const int wid  = tid >> 5;
    const int lane = tid & 31;
    const int warpM = (wid >> 2) * 64;
    const int warpN = (wid & 3) * 32;

    const uint32_t sb = smem_u32(smem);
    const uint32_t stB[3] = { sb, sb + STG, sb + 2 * STG };

    const uint32_t aOff = (uint32_t)(warpM + (lane & 15)) * 80 + ((lane >> 4) << 4);
    const uint32_t bOff = (uint32_t)(warpN + (lane & 7) + ((lane & 16) >> 1)) * 80 +
                          ((lane & 8) << 1);

    float acc[4][4][4];
#pragma unroll
    for (int i = 0; i < 4; i++)
#pragma unroll
        for (int j = 0; j < 4; j++)
#pragma unroll
            for (int e = 0; e < 4; e++) acc[i][j][e] = 0.0f;

    uint32_t f0a[4][4], f0b[4][2], f1a[4][4], f1b[4][2];

#define LOADF(fa, fb, stg, ko)                                               \
    {                                                                        \
        const uint32_t _ab = (stg) + (ko);                                   \
        const uint32_t _bb = (stg) + OFF_B + (ko);                           \
        _Pragma("unroll")                                                    \
        for (int mi = 0; mi < 4; mi++)                                       \
            ldm_x4((fa)[mi], _ab + aOff + (uint32_t)mi * (16 * 80));         \
        _Pragma("unroll")                                                    \
        for (int n2 = 0; n2 < 2; n2++) {                                     \
            uint32_t r[4];                                                   \
            ldm_x4(r, _bb + bOff + (uint32_t)n2 * (16 * 80));                \
            (fb)[n2 * 2][0] = r[0]; (fb)[n2 * 2][1] = r[1];                  \
            (fb)[n2 * 2 + 1][0] = r[2]; (fb)[n2 * 2 + 1][1] = r[3];          \
        }                                                                    \
    }
#define MMA_GRP(fa, fb)                                                      \
    {                                                                        \
        _Pragma("unroll")                                                    \
        for (int mi = 0; mi < 4; mi++)                                       \
            _Pragma("unroll")                                                \
            for (int ni = 0; ni < 4; ni++)                                   \
                mma16816(acc[mi][ni], (fa)[mi], (fb)[ni]);                   \
    }

    const int NC = kEnd >> 5;

    // prologue: stage chunks 0 and 1, then load f0 = (chunk0, ks0)
    stage_load(stB[0],         AG, lda, aBase, 0, tid);
    stage_load(stB[0] + OFF_B, BG, ldb, bBase, 0, tid);
    CPCOMMIT();
    if (NC > 1) {
        stage_load(stB[1],         AG, lda, aBase, 32, tid);
        stage_load(stB[1] + OFF_B, BG, ldb, bBase, 32, tid);
        CPCOMMIT();
        CPWAIT1();
    } else {
        CPWAIT0();
    }
    __syncthreads();
    LOADF(f0a, f0b, stB[0], 0);

    int sCur = 0, sNxt = 1, sFar = 2;   // stages of chunks c, c+1, c+2
    for (int c = 0; c < NC; c++) {
        LOADF(f1a, f1b, stB[sCur], 32);
        MMA_GRP(f0a, f0b);

        if (c + 2 < NC) {
            const int k0 = (c + 2) << 5;
            stage_load(stB[sFar],         AG, lda, aBase, k0, tid);
            stage_load(stB[sFar] + OFF_B, BG, ldb, bBase, k0, tid);
            CPCOMMIT();
            CPWAIT1();
        } else {
            CPWAIT0();
        }
        __syncthreads();

        if (c + 1 < NC) {
            LOADF(f0a, f0b, stB[sNxt], 0);
        }
        MMA_GRP(f1a, f1b);

        int t = sCur; sCur = sNxt; sNxt = sFar; sFar = t;
    }

#undef LOADF
#undef MMA_GRP

    // ---------------- epilogue ----------------
    const int mBase = warpM + (lane >> 2);
    const int nBase = warpN + (lane & 3) * 2;
    if (EMODE == 0) {
        const float sc = SCALE ? 0.03125f : 1.0f;
#pragma unroll
        for (int mi = 0; mi < 4; mi++)
#pragma unroll
            for (int ni = 0; ni < 4; ni++) {
                const float* cp = acc[mi][ni];
                int r0 = oRow + mBase + mi * 16;
                int cc = oCol + nBase + ni * 8;
                *(float2*)&C[(size_t)r0 * ldOut + cc]       = make_float2(cp[0] * sc, cp[1] * sc);
                *(float2*)&C[(size_t)(r0 + 8) * ldOut + cc] = make_float2(cp[2] * sc, cp[3] * sc);
            }
    } else if (EMODE == 2) {
#pragma unroll
        for (int mi = 0; mi < 4; mi++)
#pragma unroll
            for (int ni = 0; ni < 4; ni++) {
                const float* cp = acc[mi][ni];
#pragma unroll
                for (int h = 0; h < 2; h++) {
                    int r0 = oRow + mBase + mi * 16 + h * 8;
                    int cc = oCol + nBase + ni * 8;
                    uint32_t p = pack2h(__float2half_rn(cp[h * 2]),
                                        __float2half_rn(cp[h * 2 + 1]));
                    *(uint32_t*)&OH[(size_t)r0 * ldOut + cc] = p;
                }
            }
    } else {
        // fp16 transposed (V^T): (seq=row, e=col) -> Vt[b][e][seq]
#pragma unroll
        for (int mi = 0; mi < 4; mi++)
#pragma unroll
            for (int ni = 0; ni < 4; ni++) {
                const float* cp = acc[mi][ni];
#pragma unroll
                for (int e = 0; e < 4; e++) {
                    int row = oRow + mBase + mi * 16 + (e >> 1) * 8;
                    int col = oCol + nBase + ni * 8 + (e & 1);
                    int b = row >> 11, nloc = row & (NSEQ - 1);
                    size_t o = ((size_t)b * DOUT + col) * NSEQ + nloc;
                    OH[o] = __float2half_rn(cp[e]);
                }
            }
    }
}

// ---------------- kernels ----------------

// Merged prep: blocks [0, 16384) round x; blocks [16384, 19456) transpose W.
#define XBLOCKS (NTOK * DIN / 1024)   // 16384
__global__ void __launch_bounds__(256) prep_kernel(
    const float* __restrict__ X,
    const float* __restrict__ Wq, const float* __restrict__ Wk, const float* __restrict__ Wv)
{
    const int bid = blockIdx.x;
    if (bid < XBLOCKS) {
        size_t i4 = (size_t)bid * 256 + threadIdx.x;
        float4 v = *(const float4*)&X[i4 * 4];
        uint32_t p0 = pack2h(__float2half_rn(v.x), __float2half_rn(v.y));
        uint32_t p1 = pack2h(__float2half_rn(v.z), __float2half_rn(v.w));
        *(uint2*)&g_X[i4 * 4] = make_uint2(p0, p1);
        return;
    }
    const int w = bid - XBLOCKS;          // 0..3071
    const int z = w >> 10;
    const int rem = w & 1023;
    const int j0 = (rem & 31) * 32;       // dout
    const int i0 = (rem >> 5) * 32;       // din
    const float* W = (z == 0) ? Wq : (z == 1) ? Wk : Wv;
    __half* T = g_Wt + (size_t)z * DOUT * DIN;

    __shared__ float t[32][33];
    const int tx = threadIdx.x & 31, ty = threadIdx.x >> 5;
#pragma unroll
    for (int k = 0; k < 4; k++)
        t[ty + k * 8][tx] = W[(size_t)(i0 + ty + k * 8) * DOUT + j0 + tx];
    __syncthreads();
#pragma unroll
    for (int k = 0; k < 4; k++) {
        size_t o = (size_t)(j0 + ty + k * 8) * DIN + i0 + tx;
        T[o] = __float2half_rn(t[tx][ty + k * 8]);
    }
}

// Q and K projections only (z = 0, 1) — critical path for score.
__global__ void __launch_bounds__(256, 2) qkvqk_kernel()
{
    const int z = blockIdx.z;
    const __half* w = g_Wt + (size_t)z * DOUT * DIN;
    const int rowBase = blockIdx.y * 128;
    const int colBase = blockIdx.x * 128;
    gemm_h<2>(g_X, DIN, rowBase, w, DIN, colBase, DIN,
              nullptr, DOUT, rowBase, colBase, (z == 0) ? g_Q : g_K);
}

// V projection (transposed fp16 output) — runs on the side stream.
__global__ void __launch_bounds__(256, 2) qkvv_kernel()
{
    const __half* w = g_Wt + 2ull * DOUT * DIN;
    const int rowBase = blockIdx.y * 128;
    const int colBase = blockIdx.x * 128;
    gemm_h<1>(g_X, DIN, rowBase, w, DIN, colBase, DIN,
              nullptr, 0, rowBase, colBase, g_Vt);
}

// Scores S = (Q K^T) * 1/32 — compacted triangular grid, descending-qT (LPT).
#define NTILES 136
__global__ void __launch_bounds__(256, 2) score_kernel()
{
    const int b = blockIdx.z;
    const int t = (NTILES - 1) - (int)blockIdx.x;       // descending work order
    int qT = (int)((sqrtf(8.0f * (float)t + 1.0f) - 1.0f) * 0.5f);
    while ((qT + 1) * (qT + 2) / 2 <= t) qT++;
    while (qT * (qT + 1) / 2 > t) qT--;
    const int kT = t - qT * (qT + 1) / 2;

    gemm_h<0, true>(g_Q, DOUT, b * NSEQ + qT * 128,
                    g_K, DOUT, b * NSEQ + kT * 128, DOUT,
                    g_S + (size_t)b * NSEQ * NSEQ, NSEQ, qT * 128, kT * 128,
                    nullptr);
}

// Causal softmax over pre-scaled S; writes fp16 P zero-filled to 128 boundary.
__global__ void __launch_bounds__(256) softmax_kernel()
{
    const int row = blockIdx.x;
    const int b = row >> 11;
    const int q = row & (NSEQ - 1);
    const size_t rb = (size_t)b * NSEQ * NSEQ + (size_t)q * NSEQ;
    const float* s = g_S + rb;

    const int len = q + 1;
    const int alignedOut = (len + 127) & ~127;

    float v[8];
    float m = -1e30f;
#pragma unroll
    for (int i = 0; i < 2; i++) {
        int base = (threadIdx.x + i * 256) * 4;
        if (base < alignedOut) {
            float4 x = *(const float4*)&s[base];
            v[i * 4 + 0] = (base + 0 < len) ? x.x : -1e30f;
            v[i * 4 + 1] = (base + 1 < len) ? x.y : -1e30f;
            v[i * 4 + 2] = (base + 2 < len) ? x.z : -1e30f;
            v[i * 4 + 3] = (base + 3 < len) ? x.w : -1e30f;
        } else {
            v[i * 4] = v[i * 4 + 1] = v[i * 4 + 2] = v[i * 4 + 3] = -1e30f;
        }
#pragma unroll
        for (int e = 0; e < 4; e++) m = fmaxf(m, v[i * 4 + e]);
    }

    __shared__ float red[256];
    red[threadIdx.x] = m;
    __syncthreads();
#pragma unroll
    for (int off = 128; off > 0; off >>= 1) {
        if (threadIdx.x < off)
            red[threadIdx.x] = fmaxf(red[threadIdx.x], red[threadIdx.x + off]);
        __syncthreads();
    }
    m = red[0];
    __syncthreads();

    float sum = 0.0f;
#pragma unroll
    for (int i = 0; i < 8; i++) {
        float e = __expf(v[i] - m);
        v[i] = e;
        sum += e;
    }
    red[threadIdx.x] = sum;
    __syncthreads();
#pragma unroll
    for (int off = 128; off > 0; off >>= 1) {
        if (threadIdx.x < off)
            red[threadIdx.x] += red[threadIdx.x + off];
        __syncthreads();
    }
    const float inv = 1.0f / red[0];

#pragma unroll
    for (int i = 0; i < 2; i++) {
        int base = (threadIdx.x + i * 256) * 4;
        if (base < alignedOut) {
            uint32_t p0 = pack2h(__float2half_rn(v[i * 4] * inv),
                                 __float2half_rn(v[i * 4 + 1] * inv));
            uint32_t p1 = pack2h(__float2half_rn(v[i * 4 + 2] * inv),
                                 __float2half_rn(v[i * 4 + 3] * inv));
            *(uint2*)&g_P[rb + base] = make_uint2(p0, p1);
        }
    }
}

// context = P V, causal K extent. Longest-K CTAs (high qT) launch first.
__global__ void __launch_bounds__(256, 2) pv_kernel(float* __restrict__ out)
{
    const int b = blockIdx.z;
    const int qT = (int)(gridDim.y - 1) - blockIdx.y;   // descending work order
    gemm_h<0>(g_P, NSEQ, b * NSEQ + qT * 128,
              g_Vt, NSEQ, b * DOUT + blockIdx.x * 128,
              (qT + 1) * 128,
              out + (size_t)b * NSEQ * DOUT, DOUT, qT * 128, blockIdx.x * 128,
              nullptr);
}

// ---------------- launch ----------------
// Fork/join: the V projection is independent of score/softmax, so it runs on a
// side stream concurrently with them. Streams/events are created once on the
// first (uncaptured) call and reused; the captured calls replay the identical
// fork-join pattern (documented CUDA graph-capture cross-stream idiom).
extern "C" void kernel_launch(void* const* d_in, const int* in_sizes, int n_in,
                              void* d_out, int out_size)
{
    (void)in_sizes; (void)n_in; (void)out_size;
    const float* x  = (const float*)d_in[0];
    const float* Wq = (const float*)d_in[1];
    const float* Wk = (const float*)d_in[2];
    const float* Wv = (const float*)d_in[3];
    float* out = (float*)d_out;

    static cudaStream_t s2 = nullptr;
    static cudaEvent_t  eFork = nullptr, eJoin = nullptr;
    if (s2 == nullptr) {
        cudaStreamCreateWithFlags(&s2, cudaStreamNonBlocking);
        cudaEventCreateWithFlags(&eFork, cudaEventDisableTiming);
        cudaEventCreateWithFlags(&eJoin, cudaEventDisableTiming);
        cudaFuncSetAttribute(qkvqk_kernel, cudaFuncAttributeMaxDynamicSharedMemorySize, SMEM_SZ);
        cudaFuncSetAttribute(qkvv_kernel,  cudaFuncAttributeMaxDynamicSharedMemorySize, SMEM_SZ);
        cudaFuncSetAttribute(score_kernel, cudaFuncAttributeMaxDynamicSharedMemorySize, SMEM_SZ);
        cudaFuncSetAttribute(pv_kernel,    cudaFuncAttributeMaxDynamicSharedMemorySize, SMEM_SZ);
    }

    prep_kernel<<<XBLOCKS + 3072, 256>>>(x, Wq, Wk, Wv);

    // fork: V projection on side stream
    cudaEventRecord(eFork, 0);
    cudaStreamWaitEvent(s2, eFork, 0);
    qkvv_kernel<<<dim3(DOUT / 128, NTOK / 128, 1), 256, SMEM_SZ, s2>>>();
    cudaEventRecord(eJoin, s2);

    // main chain: Q/K projection -> scores -> softmax
    qkvqk_kernel<<<dim3(DOUT / 128, NTOK / 128, 2), 256, SMEM_SZ>>>();
    score_kernel<<<dim3(NTILES, 1, BATCH), 256, SMEM_SZ>>>();
    softmax_kernel<<<BATCH * NSEQ, 256>>>();

    // join: pv needs V^T and P
    cudaStreamWaitEvent(0, eJoin, 0);
    pv_kernel<<<dim3(DOUT / 128, NSEQ / 128, BATCH), 256, SMEM_SZ>>>(out);
}

// round 16
// speedup vs baseline: 1.0375x; 1.0178x over previous
#include <cuda_runtime.h>
#include <cuda_fp16.h>
#include <cstdint>

#define NSEQ 2048
#define DIN  1024
#define DOUT 1024
#define BATCH 8
#define NTOK  (BATCH * NSEQ)   // 16384

// ---------------- device scratch (no allocations allowed) ----------------
__device__ float g_S[(size_t)BATCH * NSEQ * NSEQ];
__device__ __half g_X [(size_t)NTOK * DIN];                 // x fp16
__device__ __half g_Wt[3ull * DOUT * DIN];                  // W^T fp16
__device__ __half g_Q [(size_t)NTOK * DOUT];                // Q fp16
__device__ __half g_K [(size_t)NTOK * DOUT];                // K fp16
__device__ __half g_Vt[(size_t)BATCH * DOUT * NSEQ];        // V^T fp16
__device__ __half g_P [(size_t)BATCH * NSEQ * NSEQ];        // P fp16

// ---------------- helpers ----------------
__device__ __forceinline__ uint32_t smem_u32(const void* p) {
    uint32_t a;
    asm("{ .reg .u64 t; cvta.to.shared.u64 t, %1; cvt.u32.u64 %0, t; }" : "=r"(a) : "l"(p));
    return a;
}
__device__ __forceinline__ void ldm_x4(uint32_t r[4], uint32_t addr) {
    asm volatile("ldmatrix.sync.aligned.m8n8.x4.shared.b16 {%0,%1,%2,%3}, [%4];"
                 : "=r"(r[0]), "=r"(r[1]), "=r"(r[2]), "=r"(r[3]) : "r"(addr));
}
__device__ __forceinline__ void mma16816(float* c, const uint32_t* a, const uint32_t* b) {
    asm volatile(
        "mma.sync.aligned.m16n8k16.row.col.f32.f16.f16.f32 "
        "{%0,%1,%2,%3}, {%4,%5,%6,%7}, {%8,%9}, {%0,%1,%2,%3};"
        : "+f"(c[0]), "+f"(c[1]), "+f"(c[2]), "+f"(c[3])
        : "r"(a[0]), "r"(a[1]), "r"(a[2]), "r"(a[3]), "r"(b[0]), "r"(b[1]));
}
#define CP16(dst, src) \
    asm volatile("cp.async.cg.shared.global [%0], [%1], 16;" :: "r"(dst), "l"(src))
#define CPCOMMIT() asm volatile("cp.async.commit_group;" ::: "memory")
#define CPWAIT1()  asm volatile("cp.async.wait_group 1;" ::: "memory")
#define CPWAIT0()  asm volatile("cp.async.wait_group 0;" ::: "memory")

__device__ __forceinline__ uint32_t pack2h(__half a, __half b) {
    return (uint32_t)__half_as_ushort(a) | ((uint32_t)__half_as_ushort(b) << 16);
}

// SMEM: 3-stage ring. Stage = A tile (128x32, 80B stride) + B tile. 20 KB/stage.
#define TBYTES   10240
#define OFF_B    10240
#define STG      20480
#define SMEM_SZ  (3 * STG)        // 61440 B -> 2 CTAs/SM

// cp.async one tile (128x32 fp16)
__device__ __forceinline__ void stage_load(
    uint32_t sT, const __half* __restrict__ T, int ld, int base, int k0, int tid)
{
#pragma unroll
    for (int i = 0; i < 2; i++) {
        int idx = tid + i * 256;
        int row = idx >> 2;
        int c   = idx & 3;
        size_t g = (size_t)(base + row) * ld + k0 + c * 8;
        CP16(sT + row * 80 + c * 16, T + g);
    }
}

// ---------------- core GEMM: fp16 x fp16 -> fp32 (R12 schedule) ----------------
// 128x128 CTA tile, 8 warps (2M x 4N), warp tile 64x32, BK=32.
// 3-stage cp.async ring + cross-barrier MMA holdback.
// EMODE: 0 = fp32 C (optionally scaled), 1 = fp16 transposed (V^T), 2 = fp16 row-major
template <int EMODE, bool SCALE = false>
__device__ __forceinline__ void gemm_h(
    const __half* __restrict__ AG, int lda, int aBase,
    const __half* __restrict__ BG, int ldb, int bBase, int kEnd,
    float* __restrict__ C, int ldOut, int oRow, int oCol,
    __half* __restrict__ OH)
{
    extern __shared__ char smem[];
    const int tid  = threadIdx.x;
    const int wid  = tid >> 5;
    const int lane = tid & 31;
    const int warpM = (wid >> 2) * 64;
    const int warpN = (wid & 3) * 32;

    const uint32_t sb = smem_u32(smem);
    const uint32_t stB[3] = { sb, sb + STG, sb + 2 * STG };

    const uint32_t aOff = (uint32_t)(warpM + (lane & 15)) * 80 + ((lane >> 4) << 4);
    const uint32_t bOff = (uint32_t)(warpN + (lane & 7) + ((lane & 16) >> 1)) * 80 +
                          ((lane & 8) << 1);

    float acc[4][4][4];
#pragma unroll
    for (int i = 0; i < 4; i++)
#pragma unroll
        for (int j = 0; j < 4; j++)
#pragma unroll
            for (int e = 0; e < 4; e++) acc[i][j][e] = 0.0f;

    uint32_t f0a[4][4], f0b[4][2], f1a[4][4], f1b[4][2];

#define LOADF(fa, fb, stg, ko)                                               \
    {                                                                        \
        const uint32_t _ab = (stg) + (ko);                                   \
        const uint32_t _bb = (stg) + OFF_B + (ko);                           \
        _Pragma("unroll")                                                    \
        for (int mi = 0; mi < 4; mi++)                                       \
            ldm_x4((fa)[mi], _ab + aOff + (uint32_t)mi * (16 * 80));         \
        _Pragma("unroll")                                                    \
        for (int n2 = 0; n2 < 2; n2++) {                                     \
            uint32_t r[4];                                                   \
            ldm_x4(r, _bb + bOff + (uint32_t)n2 * (16 * 80));                \
            (fb)[n2 * 2][0] = r[0]; (fb)[n2 * 2][1] = r[1];                  \
            (fb)[n2 * 2 + 1][0] = r[2]; (fb)[n2 * 2 + 1][1] = r[3];          \
        }                                                                    \
    }
#define MMA_GRP(fa, fb)                                                      \
    {                                                                        \
        _Pragma("unroll")                                                    \
        for (int mi = 0; mi < 4; mi++)                                       \
            _Pragma("unroll")                                                \
            for (int ni = 0; ni < 4; ni++)                                   \
                mma16816(acc[mi][ni], (fa)[mi], (fb)[ni]);                   \
    }

    const int NC = kEnd >> 5;

    // prologue: stage chunks 0 and 1, then load f0 = (chunk0, ks0)
    stage_load(stB[0],         AG, lda, aBase, 0, tid);
    stage_load(stB[0] + OFF_B, BG, ldb, bBase, 0, tid);
    CPCOMMIT();
    if (NC > 1) {
        stage_load(stB[1],         AG, lda, aBase, 32, tid);
        stage_load(stB[1] + OFF_B, BG, ldb, bBase, 32, tid);
        CPCOMMIT();
        CPWAIT1();
    } else {
        CPWAIT0();
    }
    __syncthreads();
    LOADF(f0a, f0b, stB[0], 0);

    int sCur = 0, sNxt = 1, sFar = 2;   // stages of chunks c, c+1, c+2
    for (int c = 0; c < NC; c++) {
        LOADF(f1a, f1b, stB[sCur], 32);
        MMA_GRP(f0a, f0b);

        if (c + 2 < NC) {
            const int k0 = (c + 2) << 5;
            stage_load(stB[sFar],         AG, lda, aBase, k0, tid);
            stage_load(stB[sFar] + OFF_B, BG, ldb, bBase, k0, tid);
            CPCOMMIT();
            CPWAIT1();
        } else {
            CPWAIT0();
        }
        __syncthreads();

        if (c + 1 < NC) {
            LOADF(f0a, f0b, stB[sNxt], 0);
        }
        MMA_GRP(f1a, f1b);

        int t = sCur; sCur = sNxt; sNxt = sFar; sFar = t;
    }

#undef LOADF
#undef MMA_GRP

    // ---------------- epilogue ----------------
    const int mBase = warpM + (lane >> 2);
    const int nBase = warpN + (lane & 3) * 2;
    if (EMODE == 0) {
        const float sc = SCALE ? 0.03125f : 1.0f;
#pragma unroll
        for (int mi = 0; mi < 4; mi++)
#pragma unroll
            for (int ni = 0; ni < 4; ni++) {
                const float* cp = acc[mi][ni];
                int r0 = oRow + mBase + mi * 16;
                int cc = oCol + nBase + ni * 8;
                *(float2*)&C[(size_t)r0 * ldOut + cc]       = make_float2(cp[0] * sc, cp[1] * sc);
                *(float2*)&C[(size_t)(r0 + 8) * ldOut + cc] = make_float2(cp[2] * sc, cp[3] * sc);
            }
    } else if (EMODE == 2) {
#pragma unroll
        for (int mi = 0; mi < 4; mi++)
#pragma unroll
            for (int ni = 0; ni < 4; ni++) {
                const float* cp = acc[mi][ni];
#pragma unroll
                for (int h = 0; h < 2; h++) {
                    int r0 = oRow + mBase + mi * 16 + h * 8;
                    int cc = oCol + nBase + ni * 8;
                    uint32_t p = pack2h(__float2half_rn(cp[h * 2]),
                                        __float2half_rn(cp[h * 2 + 1]));
                    *(uint32_t*)&OH[(size_t)r0 * ldOut + cc] = p;
                }
            }
    } else {
        // fp16 transposed (V^T): (seq=row, e=col) -> Vt[b][e][seq]
#pragma unroll
        for (int mi = 0; mi < 4; mi++)
#pragma unroll
            for (int ni = 0; ni < 4; ni++) {
                const float* cp = acc[mi][ni];
#pragma unroll
                for (int e = 0; e < 4; e++) {
                    int row = oRow + mBase + mi * 16 + (e >> 1) * 8;
                    int col = oCol + nBase + ni * 8 + (e & 1);
                    int b = row >> 11, nloc = row & (NSEQ - 1);
                    size_t o = ((size_t)b * DOUT + col) * NSEQ + nloc;
                    OH[o] = __float2half_rn(cp[e]);
                }
            }
    }
}

// ---------------- kernels ----------------

// Merged prep: blocks [0, 16384) round x; blocks [16384, 19456) transpose W.
#define XBLOCKS (NTOK * DIN / 1024)   // 16384
__global__ void __launch_bounds__(256) prep_kernel(
    const float* __restrict__ X,
    const float* __restrict__ Wq, const float* __restrict__ Wk, const float* __restrict__ Wv)
{
    const int bid = blockIdx.x;
    if (bid < XBLOCKS) {
        size_t i4 = (size_t)bid * 256 + threadIdx.x;
        float4 v = *(const float4*)&X[i4 * 4];
        uint32_t p0 = pack2h(__float2half_rn(v.x), __float2half_rn(v.y));
        uint32_t p1 = pack2h(__float2half_rn(v.z), __float2half_rn(v.w));
        *(uint2*)&g_X[i4 * 4] = make_uint2(p0, p1);
        return;
    }
    const int w = bid - XBLOCKS;          // 0..3071
    const int z = w >> 10;
    const int rem = w & 1023;
    const int j0 = (rem & 31) * 32;       // dout
    const int i0 = (rem >> 5) * 32;       // din
    const float* W = (z == 0) ? Wq : (z == 1) ? Wk : Wv;
    __half* T = g_Wt + (size_t)z * DOUT * DIN;

    __shared__ float t[32][33];
    const int tx = threadIdx.x & 31, ty = threadIdx.x >> 5;
#pragma unroll
    for (int k = 0; k < 4; k++)
        t[ty + k * 8][tx] = W[(size_t)(i0 + ty + k * 8) * DOUT + j0 + tx];
    __syncthreads();
#pragma unroll
    for (int k = 0; k < 4; k++) {
        size_t o = (size_t)(j0 + ty + k * 8) * DIN + i0 + tx;
        T[o] = __float2half_rn(t[tx][ty + k * 8]);
    }
}

// Q and K projections only (z = 0, 1) — critical path for score.
__global__ void __launch_bounds__(256, 2) qkvqk_kernel()
{
    const int z = blockIdx.z;
    const __half* w = g_Wt + (size_t)z * DOUT * DIN;
    const int rowBase = blockIdx.y * 128;
    const int colBase = blockIdx.x * 128;
    gemm_h<2>(g_X, DIN, rowBase, w, DIN, colBase, DIN,
              nullptr, DOUT, rowBase, colBase, (z == 0) ? g_Q : g_K);
}

// V projection (transposed fp16 output) — side stream, overlapping score+softmax.
__global__ void __launch_bounds__(256, 2) qkvv_kernel()
{
    const __half* w = g_Wt + 2ull * DOUT * DIN;
    const int rowBase = blockIdx.y * 128;
    const int colBase = blockIdx.x * 128;
    gemm_h<1>(g_X, DIN, rowBase, w, DIN, colBase, DIN,
              nullptr, 0, rowBase, colBase, g_Vt);
}

// Scores S = (Q K^T) * 1/32 — compacted triangular grid, descending-qT (LPT).
#define NTILES 136
__global__ void __launch_bounds__(256, 2) score_kernel()
{
    const int b = blockIdx.z;
    const int t = (NTILES - 1) - (int)blockIdx.x;       // descending work order
    int qT = (int)((sqrtf(8.0f * (float)t + 1.0f) - 1.0f) * 0.5f);
    while ((qT + 1) * (qT + 2) / 2 <= t) qT++;
    while (qT * (qT + 1) / 2 > t) qT--;
    const int kT = t - qT * (qT + 1) / 2;

    gemm_h<0, true>(g_Q, DOUT, b * NSEQ + qT * 128,
                    g_K, DOUT, b * NSEQ + kT * 128, DOUT,
                    g_S + (size_t)b * NSEQ * NSEQ, NSEQ, qT * 128, kT * 128,
                    nullptr);
}

// Causal softmax over pre-scaled S; writes fp16 P zero-filled to 128 boundary.
__global__ void __launch_bounds__(256) softmax_kernel()
{
    const int row = blockIdx.x;
    const int b = row >> 11;
    const int q = row & (NSEQ - 1);
    const size_t rb = (size_t)b * NSEQ * NSEQ + (size_t)q * NSEQ;
    const float* s = g_S + rb;

    const int len = q + 1;
    const int alignedOut = (len + 127) & ~127;

    float v[8];
    float m = -1e30f;
#pragma unroll
    for (int i = 0; i < 2; i++) {
        int base = (threadIdx.x + i * 256) * 4;
        if (base < alignedOut) {
            float4 x = *(const float4*)&s[base];
            v[i * 4 + 0] = (base + 0 < len) ? x.x : -1e30f;
            v[i * 4 + 1] = (base + 1 < len) ? x.y : -1e30f;
            v[i * 4 + 2] = (base + 2 < len) ? x.z : -1e30f;
            v[i * 4 + 3] = (base + 3 < len) ? x.w : -1e30f;
        } else {
            v[i * 4] = v[i * 4 + 1] = v[i * 4 + 2] = v[i * 4 + 3] = -1e30f;
        }
#pragma unroll
        for (int e = 0; e < 4; e++) m = fmaxf(m, v[i * 4 + e]);
    }

    __shared__ float red[256];
    red[threadIdx.x] = m;
    __syncthreads();
#pragma unroll
    for (int off = 128; off > 0; off >>= 1) {
        if (threadIdx.x < off)
            red[threadIdx.x] = fmaxf(red[threadIdx.x], red[threadIdx.x + off]);
        __syncthreads();
    }
    m = red[0];
    __syncthreads();

    float sum = 0.0f;
#pragma unroll
    for (int i = 0; i < 8; i++) {
        float e = __expf(v[i] - m);
        v[i] = e;
        sum += e;
    }
    red[threadIdx.x] = sum;
    __syncthreads();
#pragma unroll
    for (int off = 128; off > 0; off >>= 1) {
        if (threadIdx.x < off)
            red[threadIdx.x] += red[threadIdx.x + off];
        __syncthreads();
    }
    const float inv = 1.0f / red[0];

#pragma unroll
    for (int i = 0; i < 2; i++) {
        int base = (threadIdx.x + i * 256) * 4;
        if (base < alignedOut) {
            uint32_t p0 = pack2h(__float2half_rn(v[i * 4] * inv),
                                 __float2half_rn(v[i * 4 + 1] * inv));
            uint32_t p1 = pack2h(__float2half_rn(v[i * 4 + 2] * inv),
                                 __float2half_rn(v[i * 4 + 3] * inv));
            *(uint2*)&g_P[rb + base] = make_uint2(p0, p1);
        }
    }
}

// context = P V, causal K extent. Longest-K CTAs (high qT) launch first.
__global__ void __launch_bounds__(256, 2) pv_kernel(float* __restrict__ out)
{
    const int b = blockIdx.z;
    const int qT = (int)(gridDim.y - 1) - blockIdx.y;   // descending work order
    gemm_h<0>(g_P, NSEQ, b * NSEQ + qT * 128,
              g_Vt, NSEQ, b * DOUT + blockIdx.x * 128,
              (qT + 1) * 128,
              out + (size_t)b * NSEQ * DOUT, DOUT, qT * 128, blockIdx.x * 128,
              nullptr);
}

// ---------------- launch ----------------
// Fork placed AFTER qkvQK: the V projection overlaps score+softmax, whose idle
// resources (score tail waves, softmax's idle tensor pipe) it can fill.
extern "C" void kernel_launch(void* const* d_in, const int* in_sizes, int n_in,
                              void* d_out, int out_size)
{
    (void)in_sizes; (void)n_in; (void)out_size;
    const float* x  = (const float*)d_in[0];
    const float* Wq = (const float*)d_in[1];
    const float* Wk = (const float*)d_in[2];
    const float* Wv = (const float*)d_in[3];
    float* out = (float*)d_out;

    static cudaStream_t s2 = nullptr;
    static cudaEvent_t  eFork = nullptr, eJoin = nullptr;
    if (s2 == nullptr) {
        cudaStreamCreateWithFlags(&s2, cudaStreamNonBlocking);
        cudaEventCreateWithFlags(&eFork, cudaEventDisableTiming);
        cudaEventCreateWithFlags(&eJoin, cudaEventDisableTiming);
        cudaFuncSetAttribute(qkvqk_kernel, cudaFuncAttributeMaxDynamicSharedMemorySize, SMEM_SZ);
        cudaFuncSetAttribute(qkvv_kernel,  cudaFuncAttributeMaxDynamicSharedMemorySize, SMEM_SZ);
        cudaFuncSetAttribute(score_kernel, cudaFuncAttributeMaxDynamicSharedMemorySize, SMEM_SZ);
        cudaFuncSetAttribute(pv_kernel,    cudaFuncAttributeMaxDynamicSharedMemorySize, SMEM_SZ);
    }

    prep_kernel<<<XBLOCKS + 3072, 256>>>(x, Wq, Wk, Wv);

    // critical path first: Q/K projection
    qkvqk_kernel<<<dim3(DOUT / 128, NTOK / 128, 2), 256, SMEM_SZ>>>();

    // fork AFTER qkvQK: V projection runs concurrently with score + softmax
    cudaEventRecord(eFork, 0);
    cudaStreamWaitEvent(s2, eFork, 0);
    qkvv_kernel<<<dim3(DOUT / 128, NTOK / 128, 1), 256, SMEM_SZ, s2>>>();
    cudaEventRecord(eJoin, s2);

    // main chain: scores -> softmax (overlapped by qkvv on s2)
    score_kernel<<<dim3(NTILES, 1, BATCH), 256, SMEM_SZ>>>();
    softmax_kernel<<<BATCH * NSEQ, 256>>>();

    // join: pv needs V^T and P
    cudaStreamWaitEvent(0, eJoin, 0);
    pv_kernel<<<dim3(DOUT / 128, NSEQ / 128, BATCH), 256, SMEM_SZ>>>(out);
}